// round 6
// baseline (speedup 1.0000x reference)
#include <cuda_runtime.h>

// SSIM loss, fully fused single pass with in-kernel finalize.
// 96 planes of 512x512 fp32. Separable 3x3 Gaussian (sigma=1.5), zero pad.
// Math done in unnormalized-tap space [1, r, 1] with packed f32x2 ops;
// the W0^2 normalization is folded into the SSIM constants.

typedef unsigned long long u64;

#define HW 512
#define PLANE (HW * HW)
#define NPLANES 96
#define ROWS_PB 32
#define TPB 128
#define GRID_X (HW / ROWS_PB)        // 16
#define NBLOCKS (GRID_X * NPLANES)   // 1536

// taps: g=exp(-1/4.5); W0=g/(1+2g); W1=1/(1+2g); r=W1/W0=1/g
#define R_TAP    1.2488489f
#define S_2D     0.09474166f   // s  = W0^2  (2D separable scale)
#define TWO_S    0.18948332f   // 2s
#define S_SQ     0.00897598f   // s^2
#define TWO_S_SQ 0.01795196f   // 2 s^2
#define C1f 1.0e-4f
#define C2f 9.0e-4f

__device__ float g_partials[NBLOCKS];
__device__ unsigned int g_ticket = 0;

__device__ __forceinline__ u64 pk(float a, float b) {
    u64 r; asm("mov.b64 %0, {%1, %2};" : "=l"(r) : "f"(a), "f"(b)); return r;
}
__device__ __forceinline__ void upk(u64 v, float& a, float& b) {
    asm("mov.b64 {%0, %1}, %2;" : "=f"(a), "=f"(b) : "l"(v));
}
__device__ __forceinline__ u64 f2mul(u64 a, u64 b) {
    u64 d; asm("mul.rn.f32x2 %0, %1, %2;" : "=l"(d) : "l"(a), "l"(b)); return d;
}
__device__ __forceinline__ u64 f2add(u64 a, u64 b) {
    u64 d; asm("add.rn.f32x2 %0, %1, %2;" : "=l"(d) : "l"(a), "l"(b)); return d;
}
__device__ __forceinline__ u64 f2fma(u64 a, u64 b, u64 c) {
    u64 d; asm("fma.rn.f32x2 %0, %1, %2, %3;" : "=l"(d) : "l"(a), "l"(b), "l"(c)); return d;
}

// SSIM map + accumulate for one packed column pair, in U-space.
// mu_i = s*U_i, E_ij = s*V_ij.
__device__ __forceinline__ void emit_pair(
    u64 U1, u64 U2, u64 V11, u64 V22, u64 V12,
    u64 K2S2, u64 KM2S2, u64 K2S, u64 KS2, u64 KMS2, u64 KS, u64 KC1, u64 KC2,
    float& tA, float& tB)
{
    u64 P  = f2mul(U1, U2);                       // U1*U2
    u64 Q  = f2fma(U2, U2, f2mul(U1, U1));        // U1^2+U2^2
    u64 S  = f2add(V11, V22);
    u64 n1 = f2fma(K2S2, P, KC1);                 // 2 mu12 + C1
    u64 n2 = f2fma(K2S, V12, f2fma(KM2S2, P, KC2));   // 2 sigma12 + C2
    u64 d1 = f2fma(KS2, Q, KC1);                  // mu1^2+mu2^2 + C1
    u64 d2 = f2fma(KS, S, f2fma(KMS2, Q, KC2));   // sigma1+sigma2 + C2
    u64 num = f2mul(n1, n2);
    u64 den = f2mul(d1, d2);
    float nl, nh, dl, dh;
    upk(num, nl, nh); upk(den, dl, dh);
    tA += __fdividef(nl, dl);
    tB += __fdividef(nh, dh);
}

__global__ __launch_bounds__(TPB) void ssim_main(const float* __restrict__ img1,
                                                 const float* __restrict__ img2,
                                                 float* __restrict__ out) {
    const int plane = blockIdx.y;
    const int y0 = blockIdx.x * ROWS_PB;
    const int x0 = threadIdx.x * 4;

    const float* p1 = img1 + (size_t)plane * PLANE;
    const float* p2 = img2 + (size_t)plane * PLANE;

    const u64 RR    = pk(R_TAP, R_TAP);
    const u64 K2S2  = pk(TWO_S_SQ, TWO_S_SQ);
    const u64 KM2S2 = pk(-TWO_S_SQ, -TWO_S_SQ);
    const u64 K2S   = pk(TWO_S, TWO_S);
    const u64 KS2   = pk(S_SQ, S_SQ);
    const u64 KMS2  = pk(-S_SQ, -S_SQ);
    const u64 KS    = pk(S_2D, S_2D);
    const u64 KC1   = pk(C1f, C1f);
    const u64 KC2   = pk(C2f, C2f);

    // vertical streaming state: 5 quantities x 3 packed slots
    // slot 0 = cols (x0, x0+1), slot 1 = (x0+2, x0+3), slot 2 = halo (x0-1, x0+4)
    u64 acc0[5][3], acc1[5][3];
#pragma unroll
    for (int q = 0; q < 5; ++q)
#pragma unroll
        for (int s = 0; s < 3; ++s) { acc0[q][s] = 0ull; acc1[q][s] = 0ull; }

    float tA = 0.f, tB = 0.f;

#pragma unroll 2
    for (int j = 0; j <= ROWS_PB + 1; ++j) {
        const int y = y0 - 1 + j;
        u64 pr[5][3];
        if (y >= 0 && y < HW) {
            const float* r1 = p1 + y * HW;
            const float* r2 = p2 + y * HW;
            ulonglong2 A = *reinterpret_cast<const ulonglong2*>(r1 + x0);
            ulonglong2 B = *reinterpret_cast<const ulonglong2*>(r2 + x0);
            float aL = (x0 > 0)        ? __ldg(r1 + x0 - 1) : 0.f;
            float aR = (x0 + 4 < HW)   ? __ldg(r1 + x0 + 4) : 0.f;
            float bL = (x0 > 0)        ? __ldg(r2 + x0 - 1) : 0.f;
            float bR = (x0 + 4 < HW)   ? __ldg(r2 + x0 + 4) : 0.f;
            pr[0][0] = A.x; pr[0][1] = A.y; pr[0][2] = pk(aL, aR);
            pr[1][0] = B.x; pr[1][1] = B.y; pr[1][2] = pk(bL, bR);
        } else {
#pragma unroll
            for (int s = 0; s < 3; ++s) { pr[0][s] = 0ull; pr[1][s] = 0ull; }
        }
#pragma unroll
        for (int s = 0; s < 3; ++s) {
            pr[2][s] = f2mul(pr[0][s], pr[0][s]);   // a*a
            pr[3][s] = f2mul(pr[1][s], pr[1][s]);   // b*b
            pr[4][s] = f2mul(pr[0][s], pr[1][s]);   // a*b
        }

        if (j >= 2) {
            // vertical emit (row y-1) + horizontal filter, all unnormalized
            u64 H01[5], H23[5];
#pragma unroll
            for (int q = 0; q < 5; ++q) {
                u64 vA = f2add(acc0[q][0], pr[q][0]);   // v(c1), v(c2)
                u64 vB = f2add(acc0[q][1], pr[q][1]);   // v(c3), v(c4)
                u64 vH = f2add(acc0[q][2], pr[q][2]);   // v(c0), v(c5)
                float vAl, vAh, vBl, vBh, vHl, vHh;
                upk(vA, vAl, vAh); upk(vB, vBl, vBh); upk(vH, vHl, vHh);
                u64 L  = pk(vHl, vAl);   // (v0, v1)
                u64 M  = pk(vAh, vBl);   // (v2, v3)
                u64 Rp = pk(vBh, vHh);   // (v4, v5)
                H01[q] = f2fma(RR, vA, f2add(L, M));    // h(c1), h(c2)
                H23[q] = f2fma(RR, vB, f2add(M, Rp));   // h(c3), h(c4)
            }
            emit_pair(H01[0], H01[1], H01[2], H01[3], H01[4],
                      K2S2, KM2S2, K2S, KS2, KMS2, KS, KC1, KC2, tA, tB);
            emit_pair(H23[0], H23[1], H23[2], H23[3], H23[4],
                      K2S2, KM2S2, K2S, KS2, KMS2, KS, KC1, KC2, tA, tB);
        }

        // advance vertical pipeline
#pragma unroll
        for (int q = 0; q < 5; ++q)
#pragma unroll
            for (int s = 0; s < 3; ++s) {
                u64 t = pr[q][s];
                acc0[q][s] = f2fma(RR, t, acc1[q][s]);
                acc1[q][s] = t;
            }
    }

    // block reduction (deterministic order)
    float tsum = tA + tB;
#pragma unroll
    for (int off = 16; off; off >>= 1)
        tsum += __shfl_down_sync(0xffffffffu, tsum, off);

    __shared__ float warp_sums[TPB / 32];
    __shared__ bool is_last;
    const int lane = threadIdx.x & 31;
    const int wid = threadIdx.x >> 5;
    if (lane == 0) warp_sums[wid] = tsum;
    __syncthreads();
    if (threadIdx.x == 0) {
        float s = 0.f;
#pragma unroll
        for (int w = 0; w < TPB / 32; ++w) s += warp_sums[w];
        g_partials[blockIdx.y * GRID_X + blockIdx.x] = s;
        __threadfence();
        unsigned int t = atomicAdd(&g_ticket, 1u);
        is_last = (t == NBLOCKS - 1);
    }
    __syncthreads();

    if (is_last) {
        __threadfence();   // acquire: see all blocks' partials
        double d = 0.0;
        for (int i = threadIdx.x; i < NBLOCKS; i += TPB)
            d += (double)g_partials[i];
        __shared__ double sh[TPB];
        sh[threadIdx.x] = d;
        __syncthreads();
        for (int off = TPB / 2; off; off >>= 1) {
            if (threadIdx.x < off) sh[threadIdx.x] += sh[threadIdx.x + off];
            __syncthreads();
        }
        if (threadIdx.x == 0) {
            out[0] = (float)(1.0 - sh[0]);
            g_ticket = 0;   // reset for next graph replay
        }
    }
}

extern "C" void kernel_launch(void* const* d_in, const int* in_sizes, int n_in,
                              void* d_out, int out_size) {
    const float* img1 = (const float*)d_in[0];
    const float* img2 = (const float*)d_in[1];
    float* out = (float*)d_out;
    (void)in_sizes; (void)n_in; (void)out_size;

    dim3 grid(GRID_X, NPLANES);
    ssim_main<<<grid, TPB>>>(img1, img2, out);
}

// round 8
// speedup vs baseline: 1.0007x; 1.0007x over previous
#include <cuda_runtime.h>

// SSIM loss, fully fused single pass with in-kernel finalize.
// 96 planes of 512x512 fp32. Separable 3x3 Gaussian (sigma=1.5), zero pad.
// Math done in unnormalized-tap space [1, r, 1] with packed f32x2 ops;
// the W0^2 normalization is folded into the SSIM constants.

typedef unsigned long long u64;

#define HW 512
#define PLANE (HW * HW)
#define NPLANES 96
#define ROWS_PB 32
#define TPB 128
#define GRID_X (HW / ROWS_PB)        // 16
#define NBLOCKS (GRID_X * NPLANES)   // 1536

// taps: g=exp(-1/4.5); W0=g/(1+2g); W1=1/(1+2g); r=W1/W0=1/g
#define R_TAP    1.2488489f
#define S_2D     0.09474166f   // s  = W0^2  (2D separable scale)
#define TWO_S    0.18948332f   // 2s
#define S_SQ     0.00897598f   // s^2
#define TWO_S_SQ 0.01795196f   // 2 s^2
#define C1f 1.0e-4f
#define C2f 9.0e-4f

__device__ float g_partials[NBLOCKS];
__device__ unsigned int g_ticket = 0;

__device__ __forceinline__ u64 pk(float a, float b) {
    u64 r; asm("mov.b64 %0, {%1, %2};" : "=l"(r) : "f"(a), "f"(b)); return r;
}
__device__ __forceinline__ void upk(u64 v, float& a, float& b) {
    asm("mov.b64 {%0, %1}, %2;" : "=f"(a), "=f"(b) : "l"(v));
}
__device__ __forceinline__ u64 f2mul(u64 a, u64 b) {
    u64 d; asm("mul.rn.f32x2 %0, %1, %2;" : "=l"(d) : "l"(a), "l"(b)); return d;
}
__device__ __forceinline__ u64 f2add(u64 a, u64 b) {
    u64 d; asm("add.rn.f32x2 %0, %1, %2;" : "=l"(d) : "l"(a), "l"(b)); return d;
}
__device__ __forceinline__ u64 f2fma(u64 a, u64 b, u64 c) {
    u64 d; asm("fma.rn.f32x2 %0, %1, %2, %3;" : "=l"(d) : "l"(a), "l"(b), "l"(c)); return d;
}

// SSIM map + accumulate for one packed column pair, in U-space.
// mu_i = s*U_i, E_ij = s*V_ij.
__device__ __forceinline__ void emit_pair(
    u64 U1, u64 U2, u64 V11, u64 V22, u64 V12,
    u64 K2S2, u64 KM2S2, u64 K2S, u64 KS2, u64 KMS2, u64 KS, u64 KC1, u64 KC2,
    float& tA, float& tB)
{
    u64 P  = f2mul(U1, U2);                       // U1*U2
    u64 Q  = f2fma(U2, U2, f2mul(U1, U1));        // U1^2+U2^2
    u64 S  = f2add(V11, V22);
    u64 n1 = f2fma(K2S2, P, KC1);                 // 2 mu12 + C1
    u64 n2 = f2fma(K2S, V12, f2fma(KM2S2, P, KC2));   // 2 sigma12 + C2
    u64 d1 = f2fma(KS2, Q, KC1);                  // mu1^2+mu2^2 + C1
    u64 d2 = f2fma(KS, S, f2fma(KMS2, Q, KC2));   // sigma1+sigma2 + C2
    u64 num = f2mul(n1, n2);
    u64 den = f2mul(d1, d2);
    float nl, nh, dl, dh;
    upk(num, nl, nh); upk(den, dl, dh);
    tA += __fdividef(nl, dl);
    tB += __fdividef(nh, dh);
}

__global__ __launch_bounds__(TPB) void ssim_main(const float* __restrict__ img1,
                                                 const float* __restrict__ img2,
                                                 float* __restrict__ out) {
    const int plane = blockIdx.y;
    const int y0 = blockIdx.x * ROWS_PB;
    const int x0 = threadIdx.x * 4;

    const float* p1 = img1 + (size_t)plane * PLANE;
    const float* p2 = img2 + (size_t)plane * PLANE;

    const u64 RR    = pk(R_TAP, R_TAP);
    const u64 K2S2  = pk(TWO_S_SQ, TWO_S_SQ);
    const u64 KM2S2 = pk(-TWO_S_SQ, -TWO_S_SQ);
    const u64 K2S   = pk(TWO_S, TWO_S);
    const u64 KS2   = pk(S_SQ, S_SQ);
    const u64 KMS2  = pk(-S_SQ, -S_SQ);
    const u64 KS    = pk(S_2D, S_2D);
    const u64 KC1   = pk(C1f, C1f);
    const u64 KC2   = pk(C2f, C2f);

    // vertical streaming state: 5 quantities x 3 packed slots
    // slot 0 = cols (x0, x0+1), slot 1 = (x0+2, x0+3), slot 2 = halo (x0-1, x0+4)
    u64 acc0[5][3], acc1[5][3];
#pragma unroll
    for (int q = 0; q < 5; ++q)
#pragma unroll
        for (int s = 0; s < 3; ++s) { acc0[q][s] = 0ull; acc1[q][s] = 0ull; }

    float tA = 0.f, tB = 0.f;

#pragma unroll 2
    for (int j = 0; j <= ROWS_PB + 1; ++j) {
        const int y = y0 - 1 + j;
        u64 pr[5][3];
        if (y >= 0 && y < HW) {
            const float* r1 = p1 + y * HW;
            const float* r2 = p2 + y * HW;
            ulonglong2 A = *reinterpret_cast<const ulonglong2*>(r1 + x0);
            ulonglong2 B = *reinterpret_cast<const ulonglong2*>(r2 + x0);
            float aL = (x0 > 0)        ? __ldg(r1 + x0 - 1) : 0.f;
            float aR = (x0 + 4 < HW)   ? __ldg(r1 + x0 + 4) : 0.f;
            float bL = (x0 > 0)        ? __ldg(r2 + x0 - 1) : 0.f;
            float bR = (x0 + 4 < HW)   ? __ldg(r2 + x0 + 4) : 0.f;
            pr[0][0] = A.x; pr[0][1] = A.y; pr[0][2] = pk(aL, aR);
            pr[1][0] = B.x; pr[1][1] = B.y; pr[1][2] = pk(bL, bR);
        } else {
#pragma unroll
            for (int s = 0; s < 3; ++s) { pr[0][s] = 0ull; pr[1][s] = 0ull; }
        }
#pragma unroll
        for (int s = 0; s < 3; ++s) {
            pr[2][s] = f2mul(pr[0][s], pr[0][s]);   // a*a
            pr[3][s] = f2mul(pr[1][s], pr[1][s]);   // b*b
            pr[4][s] = f2mul(pr[0][s], pr[1][s]);   // a*b
        }

        if (j >= 2) {
            // vertical emit (row y-1) + horizontal filter, all unnormalized
            u64 H01[5], H23[5];
#pragma unroll
            for (int q = 0; q < 5; ++q) {
                u64 vA = f2add(acc0[q][0], pr[q][0]);   // v(c1), v(c2)
                u64 vB = f2add(acc0[q][1], pr[q][1]);   // v(c3), v(c4)
                u64 vH = f2add(acc0[q][2], pr[q][2]);   // v(c0), v(c5)
                float vAl, vAh, vBl, vBh, vHl, vHh;
                upk(vA, vAl, vAh); upk(vB, vBl, vBh); upk(vH, vHl, vHh);
                u64 L  = pk(vHl, vAl);   // (v0, v1)
                u64 M  = pk(vAh, vBl);   // (v2, v3)
                u64 Rp = pk(vBh, vHh);   // (v4, v5)
                H01[q] = f2fma(RR, vA, f2add(L, M));    // h(c1), h(c2)
                H23[q] = f2fma(RR, vB, f2add(M, Rp));   // h(c3), h(c4)
            }
            emit_pair(H01[0], H01[1], H01[2], H01[3], H01[4],
                      K2S2, KM2S2, K2S, KS2, KMS2, KS, KC1, KC2, tA, tB);
            emit_pair(H23[0], H23[1], H23[2], H23[3], H23[4],
                      K2S2, KM2S2, K2S, KS2, KMS2, KS, KC1, KC2, tA, tB);
        }

        // advance vertical pipeline
#pragma unroll
        for (int q = 0; q < 5; ++q)
#pragma unroll
            for (int s = 0; s < 3; ++s) {
                u64 t = pr[q][s];
                acc0[q][s] = f2fma(RR, t, acc1[q][s]);
                acc1[q][s] = t;
            }
    }

    // block reduction (deterministic order)
    float tsum = tA + tB;
#pragma unroll
    for (int off = 16; off; off >>= 1)
        tsum += __shfl_down_sync(0xffffffffu, tsum, off);

    __shared__ float warp_sums[TPB / 32];
    __shared__ bool is_last;
    const int lane = threadIdx.x & 31;
    const int wid = threadIdx.x >> 5;
    if (lane == 0) warp_sums[wid] = tsum;
    __syncthreads();
    if (threadIdx.x == 0) {
        float s = 0.f;
#pragma unroll
        for (int w = 0; w < TPB / 32; ++w) s += warp_sums[w];
        g_partials[blockIdx.y * GRID_X + blockIdx.x] = s;
        __threadfence();
        unsigned int t = atomicAdd(&g_ticket, 1u);
        is_last = (t == NBLOCKS - 1);
    }
    __syncthreads();

    if (is_last) {
        __threadfence();   // acquire: see all blocks' partials
        double d = 0.0;
        for (int i = threadIdx.x; i < NBLOCKS; i += TPB)
            d += (double)g_partials[i];
        __shared__ double sh[TPB];
        sh[threadIdx.x] = d;
        __syncthreads();
        for (int off = TPB / 2; off; off >>= 1) {
            if (threadIdx.x < off) sh[threadIdx.x] += sh[threadIdx.x + off];
            __syncthreads();
        }
        if (threadIdx.x == 0) {
            out[0] = (float)(1.0 - sh[0]);
            g_ticket = 0;   // reset for next graph replay
        }
    }
}

extern "C" void kernel_launch(void* const* d_in, const int* in_sizes, int n_in,
                              void* d_out, int out_size) {
    const float* img1 = (const float*)d_in[0];
    const float* img2 = (const float*)d_in[1];
    float* out = (float*)d_out;
    (void)in_sizes; (void)n_in; (void)out_size;

    dim3 grid(GRID_X, NPLANES);
    ssim_main<<<grid, TPB>>>(img1, img2, out);
}